// round 2
// baseline (speedup 1.0000x reference)
#include <cuda_runtime.h>
#include <math.h>

#define N_PTS 8192
#define M_PTS 2048
#define K_LAST 10
#define VARS 3

typedef unsigned long long u64;

// ---------------- packed f32x2 helpers (sm_100+) ----------------
__device__ __forceinline__ u64 pk2(float lo, float hi) {
    u64 r; asm("mov.b64 %0,{%1,%2};" : "=l"(r) : "f"(lo), "f"(hi)); return r;
}
__device__ __forceinline__ u64 dup2(float x) { return pk2(x, x); }
__device__ __forceinline__ void unpk2(u64 v, float& lo, float& hi) {
    asm("mov.b64 {%0,%1},%2;" : "=f"(lo), "=f"(hi) : "l"(v));
}
__device__ __forceinline__ u64 f2fma(u64 a, u64 b, u64 c) {
    u64 d; asm("fma.rn.f32x2 %0,%1,%2,%3;" : "=l"(d) : "l"(a), "l"(b), "l"(c)); return d;
}
__device__ __forceinline__ u64 f2mul(u64 a, u64 b) {
    u64 d; asm("mul.rn.f32x2 %0,%1,%2;" : "=l"(d) : "l"(a), "l"(b)); return d;
}

// scalar exact GELU for proj kernel
__device__ __forceinline__ float gelu(float x) {
    return 0.5f * x * (1.0f + erff(x * 0.70710678118654752f));
}

// packed GELU via Abramowitz-Stegun 7.1.26 erf (abs err <= 1.5e-7), branchless
__device__ __forceinline__ u64 gelu2(u64 x) {
    u64 ax = x & 0x7FFFFFFF7FFFFFFFULL;                 // |x|
    u64 z  = f2mul(ax, dup2(0.70710678118654752f));     // z = |x|/sqrt2
    u64 den = f2fma(z, dup2(0.3275911f), dup2(1.0f));
    float dl, dh, rl, rh;
    unpk2(den, dl, dh);
    asm("rcp.approx.f32 %0,%1;" : "=f"(rl) : "f"(dl));
    asm("rcp.approx.f32 %0,%1;" : "=f"(rh) : "f"(dh));
    u64 t = pk2(rl, rh);
    u64 z2 = f2mul(z, z);
    u64 m  = f2mul(z2, dup2(-1.4426950408889634f));     // -z^2 * log2(e)
    float ml, mh, el, eh;
    unpk2(m, ml, mh);
    asm("ex2.approx.f32 %0,%1;" : "=f"(el) : "f"(ml));
    asm("ex2.approx.f32 %0,%1;" : "=f"(eh) : "f"(mh));
    u64 e = pk2(el, eh);
    u64 p = f2fma(t, dup2(1.061405429f), dup2(-1.453152027f));
    p = f2fma(p, t, dup2(1.421413741f));
    p = f2fma(p, t, dup2(-0.284496736f));
    p = f2fma(p, t, dup2(0.254829592f));
    p = f2mul(p, t);
    u64 np = p ^ 0x8000000080000000ULL;                 // -p
    u64 u  = f2fma(np, e, dup2(1.0f));                  // erf(z) >= 0
    u64 E  = u | (x & 0x8000000080000000ULL);           // copysign(u, x)
    u64 h  = f2fma(E, dup2(0.5f), dup2(0.5f));          // 0.5 + 0.5*erf
    return f2mul(x, h);
}

// scratch
__device__ float g_f0[VARS * N_PTS * 32];
__device__ float g_acc[VARS * N_PTS * 32];

// ---------------------------------------------------------------------------
// Projection MLP: per (var,point): 8 -> gelu 64 -> 32. One warp per (var,pt).
// ---------------------------------------------------------------------------
__global__ void proj_kernel(const float* __restrict__ inp,
                            const float* __restrict__ W0, const float* __restrict__ b0,
                            const float* __restrict__ W1, const float* __restrict__ b1,
                            float* __restrict__ f0) {
    __shared__ float hs[4][64];
    int warp = threadIdx.x >> 5, lane = threadIdx.x & 31;
    int pv = blockIdx.x * 4 + warp;
    if (pv >= VARS * N_PTS) return;
    int v = pv / N_PTS, n = pv - v * N_PTS;
    const float* x = inp + n * (VARS * 8) + v * 8;
    float xr[8];
#pragma unroll
    for (int i = 0; i < 8; i++) xr[i] = x[i];
    float a0 = b0[lane], a1 = b0[lane + 32];
#pragma unroll
    for (int i = 0; i < 8; i++) {
        a0 = fmaf(xr[i], W0[i * 64 + lane], a0);
        a1 = fmaf(xr[i], W0[i * 64 + lane + 32], a1);
    }
    hs[warp][lane]      = gelu(a0);
    hs[warp][lane + 32] = gelu(a1);
    __syncwarp();
    float acc = b1[lane];
#pragma unroll
    for (int h = 0; h < 64; h++) acc = fmaf(hs[warp][h], W1[h * 32 + lane], acc);
    f0[(size_t)pv * 32 + lane] = acc;
}

// ---------------------------------------------------------------------------
// Edge MLP 36->80(gelu)->80(gelu)->32, one thread per edge, f32x2-packed
// along the output/hidden dimension. Weights natural row-major in shared
// (packed j-pairs are adjacent). h1 stored duplicated {h,h} per k in shared
// with stride 164 floats (odd float4 count -> conflict-free LDS.128).
// ---------------------------------------------------------------------------
#define TPB 256
#define H1_STRIDE 164   // floats per thread (80 u64 = 160, +4 pad)

template <int MODE>
__global__ void __launch_bounds__(TPB, 1)
edge_kernel(const float* __restrict__ Wa, const float* __restrict__ ba,
            const float* __restrict__ Wb, const float* __restrict__ bb,
            const float* __restrict__ Wc, const float* __restrict__ bc,
            const float* __restrict__ grid_in, const float* __restrict__ grid_out,
            const float* __restrict__ fsrc,
            const int* __restrict__ idxA, const int* __restrict__ idxB,
            float* __restrict__ outbuf, int E) {
    extern __shared__ float sm[];
    float* W0s = sm;            // [36][80]  2880
    float* W1s = W0s + 2880;    // [80][80]  6400
    float* W2s = W1s + 6400;    // [80][32]  2560
    float* b0s = W2s + 2560;    // 80
    float* b1s = b0s + 80;      // 80
    float* b2s = b1s + 80;      // 32
    float* h1s = sm + 12032;    // TPB * H1_STRIDE floats

    int tid = threadIdx.x;
    for (int i = tid; i < 2880; i += TPB) W0s[i] = Wa[i];
    for (int i = tid; i < 6400; i += TPB) W1s[i] = Wb[i];
    for (int i = tid; i < 2560; i += TPB) W2s[i] = Wc[i];
    if (tid < 80) { b0s[tid] = ba[tid]; b1s[tid] = bb[tid]; }
    if (tid < 32) b2s[tid] = bc[tid];
    __syncthreads();

    int e = blockIdx.x * TPB + tid;
    if (e >= E) return;
    int v = blockIdx.y;

    // ---- gather input [pos_nbr(2), pos_self(2), f[nbr](32)] ----
    float in[36];
    int segd;
    int jn = idxA[e];
    if (MODE == 0) {
        segd = idxB[e];
        in[0] = grid_in[2 * jn];   in[1] = grid_in[2 * jn + 1];
        in[2] = grid_in[2 * segd]; in[3] = grid_in[2 * segd + 1];
    } else {
        segd = e / K_LAST;
        in[0] = grid_in[2 * jn];    in[1] = grid_in[2 * jn + 1];
        in[2] = grid_out[2 * segd]; in[3] = grid_out[2 * segd + 1];
    }
    const float4* fpv = (const float4*)(fsrc + ((size_t)v * N_PTS + jn) * 32);
#pragma unroll
    for (int q = 0; q < 8; q++) {
        float4 t = fpv[q];
        in[4 + 4 * q] = t.x; in[5 + 4 * q] = t.y;
        in[6 + 4 * q] = t.z; in[7 + 4 * q] = t.w;
    }

    // ---- layer 1: 36 -> 80, all 80 outputs as 40 packed accumulators ----
    u64 acc[40];
    {
        const u64* b0v = (const u64*)b0s;
#pragma unroll
        for (int q = 0; q < 40; q++) acc[q] = b0v[q];
#pragma unroll
        for (int i = 0; i < 36; i++) {
            u64 xi = dup2(in[i]);
            const u64* w = (const u64*)(W0s + i * 80);
#pragma unroll
            for (int q = 0; q < 40; q++) acc[q] = f2fma(xi, w[q], acc[q]);
        }
    }

    // gelu + store duplicated h1 {h,h} per k (one STS.128 per j-pair)
    u64* myh = (u64*)(h1s + tid * H1_STRIDE);
#pragma unroll
    for (int q = 0; q < 40; q++) {
        u64 g = gelu2(acc[q]);
        float g0, g1; unpk2(g, g0, g1);
        ((float4*)myh)[q] = make_float4(g0, g0, g1, g1);
    }

    // ---- layers 2+3 fused: 80 -> 80(gelu) streamed into 80 -> 32 ----
    u64 out[16];
    {
        const u64* b2v = (const u64*)b2s;
#pragma unroll
        for (int q = 0; q < 16; q++) out[q] = b2v[q];
    }

#pragma unroll 1
    for (int jt = 0; jt < 10; jt++) {            // 8 h2 outputs per tile
        u64 acc2[4];
        const u64* b1v = (const u64*)(b1s + jt * 8);
#pragma unroll
        for (int q = 0; q < 4; q++) acc2[q] = b1v[q];
#pragma unroll 10
        for (int k = 0; k < 80; k += 2) {
            ulonglong2 hv = ((const ulonglong2*)myh)[k >> 1];  // {h_k,h_k},{h_k1,h_k1}
            const u64* w0 = (const u64*)(W1s + k * 80 + jt * 8);
            const u64* w1 = (const u64*)(W1s + (k + 1) * 80 + jt * 8);
#pragma unroll
            for (int q = 0; q < 4; q++) {
                acc2[q] = f2fma(hv.x, w0[q], acc2[q]);
                acc2[q] = f2fma(hv.y, w1[q], acc2[q]);
            }
        }
#pragma unroll
        for (int q = 0; q < 4; q++) {
            u64 g = gelu2(acc2[q]);
            float g0, g1; unpk2(g, g0, g1);
            u64 gd0 = dup2(g0), gd1 = dup2(g1);
            const u64* w2a = (const u64*)(W2s + (jt * 8 + 2 * q) * 32);
            const u64* w2b = (const u64*)(W2s + (jt * 8 + 2 * q + 1) * 32);
#pragma unroll
            for (int o = 0; o < 16; o++) {
                out[o] = f2fma(gd0, w2a[o], out[o]);
                out[o] = f2fma(gd1, w2b[o], out[o]);
            }
        }
    }

    // ---- scatter ----
    float* dst; float scale;
    if (MODE == 0) { dst = outbuf + ((size_t)v * N_PTS + segd) * 32; scale = 1.0f; }
    else           { dst = outbuf + (size_t)segd * (VARS * 32) + v * 32; scale = 0.1f; }
#pragma unroll
    for (int q = 0; q < 16; q++) {
        float a, b; unpk2(out[q], a, b);
        atomicAdd(dst + 2 * q,     a * scale);
        atomicAdd(dst + 2 * q + 1, b * scale);
    }
}

// f1 = segment_sum * inv_count + f0 (in place into f0)
__global__ void f1_kernel(float* __restrict__ f0, const float* __restrict__ acc,
                          const int* __restrict__ counts) {
    int idx = blockIdx.x * 256 + threadIdx.x;
    if (idx >= VARS * N_PTS * 32) return;
    int n = (idx >> 5) % N_PTS;
    int c = counts[n];
    float inv = 1.0f / (float)(c > 1 ? c : 1);
    f0[idx] = fmaf(acc[idx], inv, f0[idx]);
}

extern "C" void kernel_launch(void* const* d_in, const int* in_sizes, int n_in,
                              void* d_out, int out_size) {
    const float* inp   = (const float*)d_in[0];
    const float* gin   = (const float*)d_in[1];
    const float* gout  = (const float*)d_in[2];
    const float* pW0   = (const float*)d_in[3];
    const float* pb0   = (const float*)d_in[4];
    const float* pW1   = (const float*)d_in[5];
    const float* pb1   = (const float*)d_in[6];
    const float* i0W0  = (const float*)d_in[7];
    const float* i0b0  = (const float*)d_in[8];
    const float* i0W1  = (const float*)d_in[9];
    const float* i0b1  = (const float*)d_in[10];
    const float* i0W2  = (const float*)d_in[11];
    const float* i0b2  = (const float*)d_in[12];
    const float* i1W0  = (const float*)d_in[13];
    const float* i1b0  = (const float*)d_in[14];
    const float* i1W1  = (const float*)d_in[15];
    const float* i1b1  = (const float*)d_in[16];
    const float* i1W2  = (const float*)d_in[17];
    const float* i1b2  = (const float*)d_in[18];
    const int* nbr_index  = (const int*)d_in[19];
    const int* nbr_seg    = (const int*)d_in[20];
    const int* nbr_counts = (const int*)d_in[21];
    const int* nbr_last   = (const int*)d_in[22];
    int E = in_sizes[19];

    float *f0, *acc;
    cudaGetSymbolAddress((void**)&f0,  g_f0);
    cudaGetSymbolAddress((void**)&acc, g_acc);

    cudaMemsetAsync(acc, 0, sizeof(float) * VARS * N_PTS * 32);
    cudaMemsetAsync(d_out, 0, sizeof(float) * (size_t)out_size);

    proj_kernel<<<(VARS * N_PTS + 3) / 4, 128>>>(inp, pW0, pb0, pW1, pb1, f0);

    const int SMEM = (12032 + TPB * H1_STRIDE) * (int)sizeof(float);  // 216,064 B
    cudaFuncSetAttribute(edge_kernel<0>, cudaFuncAttributeMaxDynamicSharedMemorySize, SMEM);
    cudaFuncSetAttribute(edge_kernel<1>, cudaFuncAttributeMaxDynamicSharedMemorySize, SMEM);

    dim3 g1((unsigned)((E + TPB - 1) / TPB), VARS);
    edge_kernel<0><<<g1, TPB, SMEM>>>(i0W0, i0b0, i0W1, i0b1, i0W2, i0b2,
                                      gin, nullptr, f0, nbr_index, nbr_seg, acc, E);

    f1_kernel<<<(VARS * N_PTS * 32 + 255) / 256, 256>>>(f0, acc, nbr_counts);

    int E2 = M_PTS * K_LAST;
    dim3 g2((unsigned)((E2 + TPB - 1) / TPB), VARS);
    edge_kernel<1><<<g2, TPB, SMEM>>>(i1W0, i1b0, i1W1, i1b1, i1W2, i1b2,
                                      gin, gout, f0, nbr_last, nullptr, (float*)d_out, E2);
}

// round 3
// speedup vs baseline: 1.1901x; 1.1901x over previous
#include <cuda_runtime.h>
#include <math.h>

#define N_PTS 8192
#define M_PTS 2048
#define K_LAST 10
#define VARS 3

typedef unsigned long long u64;

// ---------------- packed f32x2 helpers (sm_100+) ----------------
__device__ __forceinline__ u64 pk2(float lo, float hi) {
    u64 r; asm("mov.b64 %0,{%1,%2};" : "=l"(r) : "f"(lo), "f"(hi)); return r;
}
__device__ __forceinline__ u64 dup2(float x) { return pk2(x, x); }
__device__ __forceinline__ void unpk2(u64 v, float& lo, float& hi) {
    asm("mov.b64 {%0,%1},%2;" : "=f"(lo), "=f"(hi) : "l"(v));
}
__device__ __forceinline__ u64 f2fma(u64 a, u64 b, u64 c) {
    u64 d; asm("fma.rn.f32x2 %0,%1,%2,%3;" : "=l"(d) : "l"(a), "l"(b), "l"(c)); return d;
}
__device__ __forceinline__ u64 f2mul(u64 a, u64 b) {
    u64 d; asm("mul.rn.f32x2 %0,%1,%2;" : "=l"(d) : "l"(a), "l"(b)); return d;
}

// scalar exact GELU for proj kernel
__device__ __forceinline__ float gelu(float x) {
    return 0.5f * x * (1.0f + erff(x * 0.70710678118654752f));
}

// packed GELU via Abramowitz-Stegun 7.1.26 erf (abs err <= 1.5e-7), branchless
__device__ __forceinline__ u64 gelu2(u64 x) {
    u64 ax = x & 0x7FFFFFFF7FFFFFFFULL;
    u64 z  = f2mul(ax, dup2(0.70710678118654752f));
    u64 den = f2fma(z, dup2(0.3275911f), dup2(1.0f));
    float dl, dh, rl, rh;
    unpk2(den, dl, dh);
    asm("rcp.approx.f32 %0,%1;" : "=f"(rl) : "f"(dl));
    asm("rcp.approx.f32 %0,%1;" : "=f"(rh) : "f"(dh));
    u64 t = pk2(rl, rh);
    u64 z2 = f2mul(z, z);
    u64 m  = f2mul(z2, dup2(-1.4426950408889634f));
    float ml, mh, el, eh;
    unpk2(m, ml, mh);
    asm("ex2.approx.f32 %0,%1;" : "=f"(el) : "f"(ml));
    asm("ex2.approx.f32 %0,%1;" : "=f"(eh) : "f"(mh));
    u64 e = pk2(el, eh);
    u64 p = f2fma(t, dup2(1.061405429f), dup2(-1.453152027f));
    p = f2fma(p, t, dup2(1.421413741f));
    p = f2fma(p, t, dup2(-0.284496736f));
    p = f2fma(p, t, dup2(0.254829592f));
    p = f2mul(p, t);
    u64 np = p ^ 0x8000000080000000ULL;
    u64 u  = f2fma(np, e, dup2(1.0f));
    u64 E  = u | (x & 0x8000000080000000ULL);
    u64 h  = f2fma(E, dup2(0.5f), dup2(0.5f));
    return f2mul(x, h);
}

// scratch
__device__ float g_f0[VARS * N_PTS * 32];
__device__ float g_acc[VARS * N_PTS * 32];

// ---------------------------------------------------------------------------
// Projection MLP: per (var,point): 8 -> gelu 64 -> 32. One warp per (var,pt).
// ---------------------------------------------------------------------------
__global__ void proj_kernel(const float* __restrict__ inp,
                            const float* __restrict__ W0, const float* __restrict__ b0,
                            const float* __restrict__ W1, const float* __restrict__ b1,
                            float* __restrict__ f0) {
    __shared__ float hs[4][64];
    int warp = threadIdx.x >> 5, lane = threadIdx.x & 31;
    int pv = blockIdx.x * 4 + warp;
    if (pv >= VARS * N_PTS) return;
    int v = pv / N_PTS, n = pv - v * N_PTS;
    const float* x = inp + n * (VARS * 8) + v * 8;
    float xr[8];
#pragma unroll
    for (int i = 0; i < 8; i++) xr[i] = x[i];
    float a0 = b0[lane], a1 = b0[lane + 32];
#pragma unroll
    for (int i = 0; i < 8; i++) {
        a0 = fmaf(xr[i], W0[i * 64 + lane], a0);
        a1 = fmaf(xr[i], W0[i * 64 + lane + 32], a1);
    }
    hs[warp][lane]      = gelu(a0);
    hs[warp][lane + 32] = gelu(a1);
    __syncwarp();
    float acc = b1[lane];
#pragma unroll
    for (int h = 0; h < 64; h++) acc = fmaf(hs[warp][h], W1[h * 32 + lane], acc);
    f0[(size_t)pv * 32 + lane] = acc;
}

// ---------------------------------------------------------------------------
// Edge MLP 36->80(gelu)->80(gelu)->32, one thread per edge, f32x2-packed.
// All uniform weight reads are LDS.128 (ulonglong2). h1 stored PLAIN (u64
// j-pairs) per thread in shared, stride 42 u64; scalar dup happens in regs
// on the ALU pipe. TPB=512 -> 16 warps/SM.
// ---------------------------------------------------------------------------
#define TPB 512
#define H1_U64 42   // u64 stride per thread (40 used + 2 pad)

template <int MODE>
__global__ void __launch_bounds__(TPB, 1)
edge_kernel(const float* __restrict__ Wa, const float* __restrict__ ba,
            const float* __restrict__ Wb, const float* __restrict__ bb,
            const float* __restrict__ Wc, const float* __restrict__ bc,
            const float* __restrict__ grid_in, const float* __restrict__ grid_out,
            const float* __restrict__ fsrc,
            const int* __restrict__ idxA, const int* __restrict__ idxB,
            float* __restrict__ outbuf, int E) {
    extern __shared__ float sm[];
    float* W0s = sm;            // [36][80]  2880
    float* W1s = W0s + 2880;    // [80][80]  6400
    float* W2s = W1s + 6400;    // [80][32]  2560
    float* b0s = W2s + 2560;    // 80
    float* b1s = b0s + 80;      // 80
    float* b2s = b1s + 80;      // 32
    float* h1s = sm + 12032;    // TPB * H1_U64 u64

    int tid = threadIdx.x;
    for (int i = tid; i < 2880; i += TPB) W0s[i] = Wa[i];
    for (int i = tid; i < 6400; i += TPB) W1s[i] = Wb[i];
    for (int i = tid; i < 2560; i += TPB) W2s[i] = Wc[i];
    if (tid < 80) { b0s[tid] = ba[tid]; b1s[tid] = bb[tid]; }
    if (tid < 32) b2s[tid] = bc[tid];
    __syncthreads();

    int e = blockIdx.x * TPB + tid;
    if (e >= E) return;
    int v = blockIdx.y;

    // ---- gather input [pos_nbr(2), pos_self(2), f[nbr](32)] ----
    float in[36];
    int segd;
    int jn = idxA[e];
    if (MODE == 0) {
        segd = idxB[e];
        in[0] = grid_in[2 * jn];   in[1] = grid_in[2 * jn + 1];
        in[2] = grid_in[2 * segd]; in[3] = grid_in[2 * segd + 1];
    } else {
        segd = e / K_LAST;
        in[0] = grid_in[2 * jn];    in[1] = grid_in[2 * jn + 1];
        in[2] = grid_out[2 * segd]; in[3] = grid_out[2 * segd + 1];
    }
    const float4* fpv = (const float4*)(fsrc + ((size_t)v * N_PTS + jn) * 32);
#pragma unroll
    for (int q = 0; q < 8; q++) {
        float4 t = fpv[q];
        in[4 + 4 * q] = t.x; in[5 + 4 * q] = t.y;
        in[6 + 4 * q] = t.z; in[7 + 4 * q] = t.w;
    }

    u64* myh = (u64*)h1s + (size_t)tid * H1_U64;

    // ---- layer 1: 36 -> 80, 10 tiles of 8 outputs (4 u64 acc) ----
#pragma unroll 1
    for (int jt = 0; jt < 10; jt++) {
        ulonglong2 bv0 = ((const ulonglong2*)(b0s + jt * 8))[0];
        ulonglong2 bv1 = ((const ulonglong2*)(b0s + jt * 8))[1];
        u64 acc0 = bv0.x, acc1 = bv0.y, acc2_ = bv1.x, acc3 = bv1.y;
#pragma unroll
        for (int i = 0; i < 36; i++) {
            u64 xi = dup2(in[i]);
            const ulonglong2* w = (const ulonglong2*)(W0s + i * 80 + jt * 8);
            ulonglong2 w01 = w[0], w23 = w[1];
            acc0  = f2fma(xi, w01.x, acc0);
            acc1  = f2fma(xi, w01.y, acc1);
            acc2_ = f2fma(xi, w23.x, acc2_);
            acc3  = f2fma(xi, w23.y, acc3);
        }
        ulonglong2 s0; s0.x = gelu2(acc0);  s0.y = gelu2(acc1);
        ulonglong2 s1; s1.x = gelu2(acc2_); s1.y = gelu2(acc3);
        ((ulonglong2*)myh)[jt * 2]     = s0;
        ((ulonglong2*)myh)[jt * 2 + 1] = s1;
    }

    // ---- layers 2+3 fused: 80 -> 80(gelu) streamed into 80 -> 32 ----
    u64 out[16];
    {
        const ulonglong2* b2v = (const ulonglong2*)b2s;
#pragma unroll
        for (int q = 0; q < 8; q++) { ulonglong2 t = b2v[q]; out[2*q] = t.x; out[2*q+1] = t.y; }
    }

#pragma unroll 1
    for (int jt = 0; jt < 10; jt++) {           // 8 h2 outputs per tile
        ulonglong2 bv0 = ((const ulonglong2*)(b1s + jt * 8))[0];
        ulonglong2 bv1 = ((const ulonglong2*)(b1s + jt * 8))[1];
        u64 a0 = bv0.x, a1 = bv0.y, a2 = bv1.x, a3 = bv1.y;
#pragma unroll
        for (int kq = 0; kq < 20; kq++) {       // 4 k values per step
            ulonglong2 hq = ((const ulonglong2*)myh)[kq];
            float h0, h1, h2, h3;
            unpk2(hq.x, h0, h1); unpk2(hq.y, h2, h3);
            u64 d0 = dup2(h0), d1 = dup2(h1), d2 = dup2(h2), d3 = dup2(h3);
            const float* wb = W1s + kq * 4 * 80 + jt * 8;
            {
                ulonglong2 wA = *(const ulonglong2*)(wb);
                ulonglong2 wB = *(const ulonglong2*)(wb + 4);
                a0 = f2fma(d0, wA.x, a0); a1 = f2fma(d0, wA.y, a1);
                a2 = f2fma(d0, wB.x, a2); a3 = f2fma(d0, wB.y, a3);
            }
            {
                ulonglong2 wA = *(const ulonglong2*)(wb + 80);
                ulonglong2 wB = *(const ulonglong2*)(wb + 84);
                a0 = f2fma(d1, wA.x, a0); a1 = f2fma(d1, wA.y, a1);
                a2 = f2fma(d1, wB.x, a2); a3 = f2fma(d1, wB.y, a3);
            }
            {
                ulonglong2 wA = *(const ulonglong2*)(wb + 160);
                ulonglong2 wB = *(const ulonglong2*)(wb + 164);
                a0 = f2fma(d2, wA.x, a0); a1 = f2fma(d2, wA.y, a1);
                a2 = f2fma(d2, wB.x, a2); a3 = f2fma(d2, wB.y, a3);
            }
            {
                ulonglong2 wA = *(const ulonglong2*)(wb + 240);
                ulonglong2 wB = *(const ulonglong2*)(wb + 244);
                a0 = f2fma(d3, wA.x, a0); a1 = f2fma(d3, wA.y, a1);
                a2 = f2fma(d3, wB.x, a2); a3 = f2fma(d3, wB.y, a3);
            }
        }
        // gelu(h2 pair) -> layer3 accumulate
        u64 gacc[4] = { a0, a1, a2, a3 };
#pragma unroll
        for (int q = 0; q < 4; q++) {
            u64 g = gelu2(gacc[q]);
            float g0, g1; unpk2(g, g0, g1);
            u64 gd0 = dup2(g0), gd1 = dup2(g1);
            const ulonglong2* w2a = (const ulonglong2*)(W2s + (jt * 8 + 2 * q) * 32);
            const ulonglong2* w2b = (const ulonglong2*)(W2s + (jt * 8 + 2 * q + 1) * 32);
#pragma unroll
            for (int o = 0; o < 8; o++) {
                ulonglong2 wa = w2a[o];
                ulonglong2 wbv = w2b[o];
                out[2 * o]     = f2fma(gd0, wa.x, out[2 * o]);
                out[2 * o + 1] = f2fma(gd0, wa.y, out[2 * o + 1]);
                out[2 * o]     = f2fma(gd1, wbv.x, out[2 * o]);
                out[2 * o + 1] = f2fma(gd1, wbv.y, out[2 * o + 1]);
            }
        }
    }

    // ---- scatter ----
    float* dst; float scale;
    if (MODE == 0) { dst = outbuf + ((size_t)v * N_PTS + segd) * 32; scale = 1.0f; }
    else           { dst = outbuf + (size_t)segd * (VARS * 32) + v * 32; scale = 0.1f; }
#pragma unroll
    for (int q = 0; q < 16; q++) {
        float a, b; unpk2(out[q], a, b);
        atomicAdd(dst + 2 * q,     a * scale);
        atomicAdd(dst + 2 * q + 1, b * scale);
    }
}

// f1 = segment_sum * inv_count + f0 (in place into f0)
__global__ void f1_kernel(float* __restrict__ f0, const float* __restrict__ acc,
                          const int* __restrict__ counts) {
    int idx = blockIdx.x * 256 + threadIdx.x;
    if (idx >= VARS * N_PTS * 32) return;
    int n = (idx >> 5) % N_PTS;
    int c = counts[n];
    float inv = 1.0f / (float)(c > 1 ? c : 1);
    f0[idx] = fmaf(acc[idx], inv, f0[idx]);
}

extern "C" void kernel_launch(void* const* d_in, const int* in_sizes, int n_in,
                              void* d_out, int out_size) {
    const float* inp   = (const float*)d_in[0];
    const float* gin   = (const float*)d_in[1];
    const float* gout  = (const float*)d_in[2];
    const float* pW0   = (const float*)d_in[3];
    const float* pb0   = (const float*)d_in[4];
    const float* pW1   = (const float*)d_in[5];
    const float* pb1   = (const float*)d_in[6];
    const float* i0W0  = (const float*)d_in[7];
    const float* i0b0  = (const float*)d_in[8];
    const float* i0W1  = (const float*)d_in[9];
    const float* i0b1  = (const float*)d_in[10];
    const float* i0W2  = (const float*)d_in[11];
    const float* i0b2  = (const float*)d_in[12];
    const float* i1W0  = (const float*)d_in[13];
    const float* i1b0  = (const float*)d_in[14];
    const float* i1W1  = (const float*)d_in[15];
    const float* i1b1  = (const float*)d_in[16];
    const float* i1W2  = (const float*)d_in[17];
    const float* i1b2  = (const float*)d_in[18];
    const int* nbr_index  = (const int*)d_in[19];
    const int* nbr_seg    = (const int*)d_in[20];
    const int* nbr_counts = (const int*)d_in[21];
    const int* nbr_last   = (const int*)d_in[22];
    int E = in_sizes[19];

    float *f0, *acc;
    cudaGetSymbolAddress((void**)&f0,  g_f0);
    cudaGetSymbolAddress((void**)&acc, g_acc);

    cudaMemsetAsync(acc, 0, sizeof(float) * VARS * N_PTS * 32);
    cudaMemsetAsync(d_out, 0, sizeof(float) * (size_t)out_size);

    proj_kernel<<<(VARS * N_PTS + 3) / 4, 128>>>(inp, pW0, pb0, pW1, pb1, f0);

    const int SMEM = 12032 * (int)sizeof(float) + TPB * H1_U64 * (int)sizeof(u64); // 220,160 B
    cudaFuncSetAttribute(edge_kernel<0>, cudaFuncAttributeMaxDynamicSharedMemorySize, SMEM);
    cudaFuncSetAttribute(edge_kernel<1>, cudaFuncAttributeMaxDynamicSharedMemorySize, SMEM);

    dim3 g1((unsigned)((E + TPB - 1) / TPB), VARS);
    edge_kernel<0><<<g1, TPB, SMEM>>>(i0W0, i0b0, i0W1, i0b1, i0W2, i0b2,
                                      gin, nullptr, f0, nbr_index, nbr_seg, acc, E);

    f1_kernel<<<(VARS * N_PTS * 32 + 255) / 256, 256>>>(f0, acc, nbr_counts);

    int E2 = M_PTS * K_LAST;
    dim3 g2((unsigned)((E2 + TPB - 1) / TPB), VARS);
    edge_kernel<1><<<g2, TPB, SMEM>>>(i1W0, i1b0, i1W1, i1b1, i1W2, i1b2,
                                      gin, gout, f0, nbr_last, nullptr, (float*)d_out, E2);
}

// round 4
// speedup vs baseline: 1.4172x; 1.1909x over previous
#include <cuda_runtime.h>
#include <math.h>

#define N_PTS 8192
#define M_PTS 2048
#define K_LAST 10
#define VARS 3

typedef unsigned long long u64;

// ---------------- packed f32x2 helpers (sm_100+) ----------------
__device__ __forceinline__ u64 pk2(float lo, float hi) {
    u64 r; asm("mov.b64 %0,{%1,%2};" : "=l"(r) : "f"(lo), "f"(hi)); return r;
}
__device__ __forceinline__ u64 dup2(float x) { return pk2(x, x); }
__device__ __forceinline__ void unpk2(u64 v, float& lo, float& hi) {
    asm("mov.b64 {%0,%1},%2;" : "=f"(lo), "=f"(hi) : "l"(v));
}
__device__ __forceinline__ u64 f2fma(u64 a, u64 b, u64 c) {
    u64 d; asm("fma.rn.f32x2 %0,%1,%2,%3;" : "=l"(d) : "l"(a), "l"(b), "l"(c)); return d;
}
__device__ __forceinline__ u64 f2mul(u64 a, u64 b) {
    u64 d; asm("mul.rn.f32x2 %0,%1,%2;" : "=l"(d) : "l"(a), "l"(b)); return d;
}

// scalar exact GELU for proj kernel
__device__ __forceinline__ float gelu(float x) {
    return 0.5f * x * (1.0f + erff(x * 0.70710678118654752f));
}

// packed GELU via Abramowitz-Stegun 7.1.26 erf (abs err <= 1.5e-7), branchless
__device__ __forceinline__ u64 gelu2(u64 x) {
    u64 ax = x & 0x7FFFFFFF7FFFFFFFULL;
    u64 z  = f2mul(ax, dup2(0.70710678118654752f));
    u64 den = f2fma(z, dup2(0.3275911f), dup2(1.0f));
    float dl, dh, rl, rh;
    unpk2(den, dl, dh);
    asm("rcp.approx.f32 %0,%1;" : "=f"(rl) : "f"(dl));
    asm("rcp.approx.f32 %0,%1;" : "=f"(rh) : "f"(dh));
    u64 t = pk2(rl, rh);
    u64 z2 = f2mul(z, z);
    u64 m  = f2mul(z2, dup2(-1.4426950408889634f));
    float ml, mh, el, eh;
    unpk2(m, ml, mh);
    asm("ex2.approx.f32 %0,%1;" : "=f"(el) : "f"(ml));
    asm("ex2.approx.f32 %0,%1;" : "=f"(eh) : "f"(mh));
    u64 e = pk2(el, eh);
    u64 p = f2fma(t, dup2(1.061405429f), dup2(-1.453152027f));
    p = f2fma(p, t, dup2(1.421413741f));
    p = f2fma(p, t, dup2(-0.284496736f));
    p = f2fma(p, t, dup2(0.254829592f));
    p = f2mul(p, t);
    u64 np = p ^ 0x8000000080000000ULL;
    u64 u  = f2fma(np, e, dup2(1.0f));
    u64 E  = u | (x & 0x8000000080000000ULL);
    u64 h  = f2fma(E, dup2(0.5f), dup2(0.5f));
    return f2mul(x, h);
}

// scratch
__device__ float g_f0[VARS * N_PTS * 32];
__device__ float g_acc[VARS * N_PTS * 32];

// ---------------------------------------------------------------------------
// Projection MLP: per (var,point): 8 -> gelu 64 -> 32. One warp per (var,pt).
// ---------------------------------------------------------------------------
__global__ void proj_kernel(const float* __restrict__ inp,
                            const float* __restrict__ W0, const float* __restrict__ b0,
                            const float* __restrict__ W1, const float* __restrict__ b1,
                            float* __restrict__ f0) {
    __shared__ float hs[4][64];
    int warp = threadIdx.x >> 5, lane = threadIdx.x & 31;
    int pv = blockIdx.x * 4 + warp;
    if (pv >= VARS * N_PTS) return;
    int v = pv / N_PTS, n = pv - v * N_PTS;
    const float* x = inp + n * (VARS * 8) + v * 8;
    float xr[8];
#pragma unroll
    for (int i = 0; i < 8; i++) xr[i] = x[i];
    float a0 = b0[lane], a1 = b0[lane + 32];
#pragma unroll
    for (int i = 0; i < 8; i++) {
        a0 = fmaf(xr[i], W0[i * 64 + lane], a0);
        a1 = fmaf(xr[i], W0[i * 64 + lane + 32], a1);
    }
    hs[warp][lane]      = gelu(a0);
    hs[warp][lane + 32] = gelu(a1);
    __syncwarp();
    float acc = b1[lane];
#pragma unroll
    for (int h = 0; h < 64; h++) acc = fmaf(hs[warp][h], W1[h * 32 + lane], acc);
    f0[(size_t)pv * 32 + lane] = acc;
}

// ---------------------------------------------------------------------------
// Edge MLP 36->80(gelu)->80(gelu)->32. TWO edges per thread: every weight
// LDS.128 from shared feeds FMAs for both edges (weight traffic halved per
// edge, 2 independent dependency chains). f32x2-packed along hidden dim.
// h1 per edge-slot in shared (stride 42 u64, odd float4 -> conflict-free).
// ---------------------------------------------------------------------------
#define TPB 256
#define EPT 2
#define H1_U64 42

template <int MODE>
__global__ void __launch_bounds__(TPB, 1)
edge_kernel(const float* __restrict__ Wa, const float* __restrict__ ba,
            const float* __restrict__ Wb, const float* __restrict__ bb,
            const float* __restrict__ Wc, const float* __restrict__ bc,
            const float* __restrict__ grid_in, const float* __restrict__ grid_out,
            const float* __restrict__ fsrc,
            const int* __restrict__ idxA, const int* __restrict__ idxB,
            float* __restrict__ outbuf, int E) {
    extern __shared__ float sm[];
    float* W0s = sm;            // [36][80]  2880
    float* W1s = W0s + 2880;    // [80][80]  6400
    float* W2s = W1s + 6400;    // [80][32]  2560
    float* b0s = W2s + 2560;    // 80
    float* b1s = b0s + 80;      // 80
    float* b2s = b1s + 80;      // 32
    float* h1s = sm + 12032;    // TPB*EPT*H1_U64 u64

    int tid = threadIdx.x;
    for (int i = tid; i < 2880; i += TPB) W0s[i] = Wa[i];
    for (int i = tid; i < 6400; i += TPB) W1s[i] = Wb[i];
    for (int i = tid; i < 2560; i += TPB) W2s[i] = Wc[i];
    if (tid < 80) { b0s[tid] = ba[tid]; b1s[tid] = bb[tid]; }
    if (tid < 32) b2s[tid] = bc[tid];
    __syncthreads();

    int v = blockIdx.y;
    int ebase = blockIdx.x * (TPB * EPT) + tid;
    int eidx[EPT];
    bool val[EPT];
    int jn[EPT], segd[EPT];
#pragma unroll
    for (int ed = 0; ed < EPT; ed++) {
        eidx[ed] = ebase + ed * TPB;
        val[ed] = eidx[ed] < E;
        int e = val[ed] ? eidx[ed] : 0;
        eidx[ed] = e;
        jn[ed] = idxA[e];
        segd[ed] = (MODE == 0) ? idxB[e] : e / K_LAST;
    }

    // ---- gather inputs ----
    float in[EPT][36];
#pragma unroll
    for (int ed = 0; ed < EPT; ed++) {
        if (MODE == 0) {
            in[ed][0] = grid_in[2 * jn[ed]];    in[ed][1] = grid_in[2 * jn[ed] + 1];
            in[ed][2] = grid_in[2 * segd[ed]];  in[ed][3] = grid_in[2 * segd[ed] + 1];
        } else {
            in[ed][0] = grid_in[2 * jn[ed]];    in[ed][1] = grid_in[2 * jn[ed] + 1];
            in[ed][2] = grid_out[2 * segd[ed]]; in[ed][3] = grid_out[2 * segd[ed] + 1];
        }
        const float4* fpv = (const float4*)(fsrc + ((size_t)v * N_PTS + jn[ed]) * 32);
#pragma unroll
        for (int q = 0; q < 8; q++) {
            float4 t = fpv[q];
            in[ed][4 + 4 * q] = t.x; in[ed][5 + 4 * q] = t.y;
            in[ed][6 + 4 * q] = t.z; in[ed][7 + 4 * q] = t.w;
        }
    }

    u64* myh[EPT];
#pragma unroll
    for (int ed = 0; ed < EPT; ed++)
        myh[ed] = (u64*)h1s + (size_t)(tid + ed * TPB) * H1_U64;

    // ---- layer 1: 36 -> 80, 10 tiles of 8 outputs, weights shared by edges ----
#pragma unroll 1
    for (int jt = 0; jt < 10; jt++) {
        ulonglong2 bv0 = ((const ulonglong2*)(b0s + jt * 8))[0];
        ulonglong2 bv1 = ((const ulonglong2*)(b0s + jt * 8))[1];
        u64 a[EPT][4];
#pragma unroll
        for (int ed = 0; ed < EPT; ed++) {
            a[ed][0] = bv0.x; a[ed][1] = bv0.y; a[ed][2] = bv1.x; a[ed][3] = bv1.y;
        }
#pragma unroll
        for (int i = 0; i < 36; i++) {
            const ulonglong2* w = (const ulonglong2*)(W0s + i * 80 + jt * 8);
            ulonglong2 w01 = w[0], w23 = w[1];
#pragma unroll
            for (int ed = 0; ed < EPT; ed++) {
                u64 xi = dup2(in[ed][i]);
                a[ed][0] = f2fma(xi, w01.x, a[ed][0]);
                a[ed][1] = f2fma(xi, w01.y, a[ed][1]);
                a[ed][2] = f2fma(xi, w23.x, a[ed][2]);
                a[ed][3] = f2fma(xi, w23.y, a[ed][3]);
            }
        }
#pragma unroll
        for (int ed = 0; ed < EPT; ed++) {
            ulonglong2 s0; s0.x = gelu2(a[ed][0]); s0.y = gelu2(a[ed][1]);
            ulonglong2 s1; s1.x = gelu2(a[ed][2]); s1.y = gelu2(a[ed][3]);
            ((ulonglong2*)myh[ed])[jt * 2]     = s0;
            ((ulonglong2*)myh[ed])[jt * 2 + 1] = s1;
        }
    }

    // ---- layers 2+3 fused ----
    u64 out[EPT][16];
    {
        const ulonglong2* b2v = (const ulonglong2*)b2s;
#pragma unroll
        for (int q = 0; q < 8; q++) {
            ulonglong2 t = b2v[q];
#pragma unroll
            for (int ed = 0; ed < EPT; ed++) { out[ed][2*q] = t.x; out[ed][2*q+1] = t.y; }
        }
    }

#pragma unroll 1
    for (int jt = 0; jt < 10; jt++) {
        ulonglong2 bv0 = ((const ulonglong2*)(b1s + jt * 8))[0];
        ulonglong2 bv1 = ((const ulonglong2*)(b1s + jt * 8))[1];
        u64 a[EPT][4];
#pragma unroll
        for (int ed = 0; ed < EPT; ed++) {
            a[ed][0] = bv0.x; a[ed][1] = bv0.y; a[ed][2] = bv1.x; a[ed][3] = bv1.y;
        }
#pragma unroll
        for (int kq = 0; kq < 20; kq++) {
            const float* wb = W1s + kq * 4 * 80 + jt * 8;
            ulonglong2 wA0 = *(const ulonglong2*)(wb);
            ulonglong2 wB0 = *(const ulonglong2*)(wb + 4);
            ulonglong2 wA1 = *(const ulonglong2*)(wb + 80);
            ulonglong2 wB1 = *(const ulonglong2*)(wb + 84);
            ulonglong2 wA2 = *(const ulonglong2*)(wb + 160);
            ulonglong2 wB2 = *(const ulonglong2*)(wb + 164);
            ulonglong2 wA3 = *(const ulonglong2*)(wb + 240);
            ulonglong2 wB3 = *(const ulonglong2*)(wb + 244);
#pragma unroll
            for (int ed = 0; ed < EPT; ed++) {
                ulonglong2 hq = ((const ulonglong2*)myh[ed])[kq];
                float h0, h1, h2, h3;
                unpk2(hq.x, h0, h1); unpk2(hq.y, h2, h3);
                u64 d0 = dup2(h0), d1 = dup2(h1), d2 = dup2(h2), d3 = dup2(h3);
                a[ed][0] = f2fma(d0, wA0.x, a[ed][0]); a[ed][1] = f2fma(d0, wA0.y, a[ed][1]);
                a[ed][2] = f2fma(d0, wB0.x, a[ed][2]); a[ed][3] = f2fma(d0, wB0.y, a[ed][3]);
                a[ed][0] = f2fma(d1, wA1.x, a[ed][0]); a[ed][1] = f2fma(d1, wA1.y, a[ed][1]);
                a[ed][2] = f2fma(d1, wB1.x, a[ed][2]); a[ed][3] = f2fma(d1, wB1.y, a[ed][3]);
                a[ed][0] = f2fma(d2, wA2.x, a[ed][0]); a[ed][1] = f2fma(d2, wA2.y, a[ed][1]);
                a[ed][2] = f2fma(d2, wB2.x, a[ed][2]); a[ed][3] = f2fma(d2, wB2.y, a[ed][3]);
                a[ed][0] = f2fma(d3, wA3.x, a[ed][0]); a[ed][1] = f2fma(d3, wA3.y, a[ed][1]);
                a[ed][2] = f2fma(d3, wB3.x, a[ed][2]); a[ed][3] = f2fma(d3, wB3.y, a[ed][3]);
            }
        }
        // gelu(h2) -> layer3, weights shared by edges
#pragma unroll
        for (int q = 0; q < 4; q++) {
            u64 gd0[EPT], gd1[EPT];
#pragma unroll
            for (int ed = 0; ed < EPT; ed++) {
                u64 g = gelu2(a[ed][q]);
                float g0, g1; unpk2(g, g0, g1);
                gd0[ed] = dup2(g0); gd1[ed] = dup2(g1);
            }
            const ulonglong2* w2a = (const ulonglong2*)(W2s + (jt * 8 + 2 * q) * 32);
            const ulonglong2* w2b = (const ulonglong2*)(W2s + (jt * 8 + 2 * q + 1) * 32);
#pragma unroll
            for (int o = 0; o < 8; o++) {
                ulonglong2 wa = w2a[o];
                ulonglong2 wbv = w2b[o];
#pragma unroll
                for (int ed = 0; ed < EPT; ed++) {
                    out[ed][2*o]   = f2fma(gd0[ed], wa.x,  out[ed][2*o]);
                    out[ed][2*o+1] = f2fma(gd0[ed], wa.y,  out[ed][2*o+1]);
                    out[ed][2*o]   = f2fma(gd1[ed], wbv.x, out[ed][2*o]);
                    out[ed][2*o+1] = f2fma(gd1[ed], wbv.y, out[ed][2*o+1]);
                }
            }
        }
    }

    // ---- scatter ----
#pragma unroll
    for (int ed = 0; ed < EPT; ed++) {
        if (!val[ed]) continue;
        float* dst; float scale;
        if (MODE == 0) { dst = outbuf + ((size_t)v * N_PTS + segd[ed]) * 32; scale = 1.0f; }
        else           { dst = outbuf + (size_t)segd[ed] * (VARS * 32) + v * 32; scale = 0.1f; }
#pragma unroll
        for (int q = 0; q < 16; q++) {
            float a, b; unpk2(out[ed][q], a, b);
            atomicAdd(dst + 2 * q,     a * scale);
            atomicAdd(dst + 2 * q + 1, b * scale);
        }
    }
}

// f1 = segment_sum * inv_count + f0 (in place into f0)
__global__ void f1_kernel(float* __restrict__ f0, const float* __restrict__ acc,
                          const int* __restrict__ counts) {
    int idx = blockIdx.x * 256 + threadIdx.x;
    if (idx >= VARS * N_PTS * 32) return;
    int n = (idx >> 5) % N_PTS;
    int c = counts[n];
    float inv = 1.0f / (float)(c > 1 ? c : 1);
    f0[idx] = fmaf(acc[idx], inv, f0[idx]);
}

extern "C" void kernel_launch(void* const* d_in, const int* in_sizes, int n_in,
                              void* d_out, int out_size) {
    const float* inp   = (const float*)d_in[0];
    const float* gin   = (const float*)d_in[1];
    const float* gout  = (const float*)d_in[2];
    const float* pW0   = (const float*)d_in[3];
    const float* pb0   = (const float*)d_in[4];
    const float* pW1   = (const float*)d_in[5];
    const float* pb1   = (const float*)d_in[6];
    const float* i0W0  = (const float*)d_in[7];
    const float* i0b0  = (const float*)d_in[8];
    const float* i0W1  = (const float*)d_in[9];
    const float* i0b1  = (const float*)d_in[10];
    const float* i0W2  = (const float*)d_in[11];
    const float* i0b2  = (const float*)d_in[12];
    const float* i1W0  = (const float*)d_in[13];
    const float* i1b0  = (const float*)d_in[14];
    const float* i1W1  = (const float*)d_in[15];
    const float* i1b1  = (const float*)d_in[16];
    const float* i1W2  = (const float*)d_in[17];
    const float* i1b2  = (const float*)d_in[18];
    const int* nbr_index  = (const int*)d_in[19];
    const int* nbr_seg    = (const int*)d_in[20];
    const int* nbr_counts = (const int*)d_in[21];
    const int* nbr_last   = (const int*)d_in[22];
    int E = in_sizes[19];

    float *f0, *acc;
    cudaGetSymbolAddress((void**)&f0,  g_f0);
    cudaGetSymbolAddress((void**)&acc, g_acc);

    cudaMemsetAsync(acc, 0, sizeof(float) * VARS * N_PTS * 32);
    cudaMemsetAsync(d_out, 0, sizeof(float) * (size_t)out_size);

    proj_kernel<<<(VARS * N_PTS + 3) / 4, 128>>>(inp, pW0, pb0, pW1, pb1, f0);

    const int SMEM = 12032 * (int)sizeof(float) + TPB * EPT * H1_U64 * (int)sizeof(u64); // 220,160 B
    cudaFuncSetAttribute(edge_kernel<0>, cudaFuncAttributeMaxDynamicSharedMemorySize, SMEM);
    cudaFuncSetAttribute(edge_kernel<1>, cudaFuncAttributeMaxDynamicSharedMemorySize, SMEM);

    const int EPB = TPB * EPT;
    dim3 g1((unsigned)((E + EPB - 1) / EPB), VARS);
    edge_kernel<0><<<g1, TPB, SMEM>>>(i0W0, i0b0, i0W1, i0b1, i0W2, i0b2,
                                      gin, nullptr, f0, nbr_index, nbr_seg, acc, E);

    f1_kernel<<<(VARS * N_PTS * 32 + 255) / 256, 256>>>(f0, acc, nbr_counts);

    int E2 = M_PTS * K_LAST;
    dim3 g2((unsigned)((E2 + EPB - 1) / EPB), VARS);
    edge_kernel<1><<<g2, TPB, SMEM>>>(i1W0, i1b0, i1W1, i1b1, i1W2, i1b2,
                                      gin, gout, f0, nbr_last, nullptr, (float*)d_out, E2);
}